// round 2
// baseline (speedup 1.0000x reference)
#include <cuda_runtime.h>
#include <math.h>

#define NPTS   65536
#define CDIM   256
#define KCODES 2048

#define MT 128      // points per block
#define KT 64       // codes per chunk
#define TH 512      // threads per block (main kernel)
#define ESP 260     // padded codebook smem row (floats)

// scratch (no allocations allowed)
__device__ int    g_idx[NPTS];
__device__ float  g_cbn[KCODES];
__device__ int    g_cnt[KCODES];
__device__ double g_loss;

// offsets in d_out (fp32): [z_q_st (16,777,216) | loss | perplexity | encodings (134,217,728)]
#define OFF_LOSS 16777216
#define OFF_PERP 16777217
#define OFF_ENC  16777218

// ---------------- codebook squared norms + zero counters ----------------
__global__ void k_prep(const float* __restrict__ cb) {
    int k = blockIdx.x * blockDim.x + threadIdx.x;
    if (k < KCODES) {
        const float* row = cb + (size_t)k * CDIM;
        float s = 0.f;
        #pragma unroll 8
        for (int c = 0; c < CDIM; ++c) {
            float t = row[c];
            s = __fadd_rn(s, __fmul_rn(t, t));
        }
        g_cbn[k] = s;
        g_cnt[k] = 0;
    }
    if (k == 0) g_loss = 0.0;
}

// ---------------- fused distance GEMM + argmin ----------------
// d[n,k] = fl( fl(A_n - 2*M[n,k]) + B_k ), argmin over k with first-index ties.
__global__ __launch_bounds__(TH, 1)
void k_argmin(const float* __restrict__ z, const float* __restrict__ cb) {
    extern __shared__ float sm[];
    float* zs = sm;                       // [256][128] : z tile, c-major
    float* es = zs + 256 * 128;           // [64][ESP]  : codebook chunk, padded
    float* bs = es + 64 * ESP;            // [64]       : ||e||^2 chunk
    float* as = bs + 64;                  // [128]      : A_n

    const int tid = threadIdx.x;
    const int tk  = tid & 15;             // 0..15  (code groups)
    const int tn  = tid >> 4;             // 0..31  (point groups, 4 each)

    const int blk = blockIdx.x;           // 0..511
    const int b   = blk >> 3;
    const int hw0 = (blk & 7) << 7;       // 128 contiguous hw
    const int n0  = blk * MT;

    const float* zb = z + ((size_t)b * CDIM) * 1024 + hw0;

    // ---- load z tile (coalesced float4), store as zs[c][j] ----
    for (int e = tid; e < 256 * 32; e += TH) {
        int c  = e >> 5;
        int j4 = (e & 31) << 2;
        float4 v = *(const float4*)(zb + (size_t)c * 1024 + j4);
        *(float4*)&zs[c * 128 + j4] = v;
    }
    __syncthreads();

    // ---- A_n = sum_c z^2, strided partials + butterfly tree ----
    if (tid < MT) {
        float p[32];
        #pragma unroll
        for (int l = 0; l < 32; ++l) p[l] = 0.f;
        #pragma unroll
        for (int i = 0; i < 8; ++i) {
            #pragma unroll
            for (int l = 0; l < 32; ++l) {
                float t = zs[(l + 32 * i) * 128 + tid];
                p[l] = __fadd_rn(p[l], __fmul_rn(t, t));
            }
        }
        #pragma unroll
        for (int off = 16; off >= 1; off >>= 1) {
            #pragma unroll
            for (int l = 0; l < 16; ++l) {
                if (l < off) p[l] = __fadd_rn(p[l], p[l + off]);
            }
        }
        as[tid] = p[0];
    }
    __syncthreads();

    float Ar[4];
    #pragma unroll
    for (int r = 0; r < 4; ++r) Ar[r] = as[tn * 4 + r];

    float mval[4];
    int   midx[4];
    #pragma unroll
    for (int r = 0; r < 4; ++r) { mval[r] = 3.4e38f; midx[r] = 0; }

    for (int kb = 0; kb < KCODES; kb += KT) {
        __syncthreads();  // previous chunk's readers done before overwrite
        // load 64 codebook rows (coalesced), padded rows kill bank conflicts
        for (int e = tid; e < 64 * 64; e += TH) {
            int j  = e >> 6;
            int c4 = (e & 63) << 2;
            float4 v = *(const float4*)(cb + (size_t)(kb + j) * CDIM + c4);
            *(float4*)&es[j * ESP + c4] = v;
        }
        if (tid < KT) bs[tid] = g_cbn[kb + tid];
        __syncthreads();

        float acc[4][4];
        #pragma unroll
        for (int r = 0; r < 4; ++r)
            #pragma unroll
            for (int q = 0; q < 4; ++q) acc[r][q] = 0.f;

        #pragma unroll 4
        for (int c0 = 0; c0 < 256; c0 += 4) {
            float4 zf[4], ef[4];
            #pragma unroll
            for (int i = 0; i < 4; ++i)
                zf[i] = *(float4*)&zs[(c0 + i) * 128 + tn * 4];
            #pragma unroll
            for (int q = 0; q < 4; ++q)
                ef[q] = *(float4*)&es[(tk + 16 * q) * ESP + c0];
            #pragma unroll
            for (int i = 0; i < 4; ++i) {
                float z0 = ((const float*)&zf[i])[0];
                float z1 = ((const float*)&zf[i])[1];
                float z2 = ((const float*)&zf[i])[2];
                float z3 = ((const float*)&zf[i])[3];
                #pragma unroll
                for (int q = 0; q < 4; ++q) {
                    float ev = ((const float*)&ef[q])[i];
                    acc[0][q] = fmaf(z0, ev, acc[0][q]);
                    acc[1][q] = fmaf(z1, ev, acc[1][q]);
                    acc[2][q] = fmaf(z2, ev, acc[2][q]);
                    acc[3][q] = fmaf(z3, ev, acc[3][q]);
                }
            }
        }

        // merge this chunk into running argmin (k ascending within thread)
        #pragma unroll
        for (int q = 0; q < 4; ++q) {
            int j = tk + 16 * q;
            int k = kb + j;
            float Bk = bs[j];
            #pragma unroll
            for (int r = 0; r < 4; ++r) {
                float d = __fadd_rn(__fadd_rn(Ar[r], -2.0f * acc[r][q]), Bk);
                if (d < mval[r]) { mval[r] = d; midx[r] = k; }
            }
        }
    }

    // ---- cross-thread (tk) reduction, tie -> smallest k ----
    __syncthreads();
    float* rv  = es;                    // reuse es: 128*16 floats
    int*   rki = (int*)(es + MT * 16);  // + 128*16 ints
    #pragma unroll
    for (int r = 0; r < 4; ++r) {
        int n = tn * 4 + r;
        rv [n * 16 + tk] = mval[r];
        rki[n * 16 + tk] = midx[r];
    }
    __syncthreads();
    if (tid < MT) {
        float bv = rv[tid * 16];
        int   bi = rki[tid * 16];
        #pragma unroll
        for (int t = 1; t < 16; ++t) {
            float v = rv[tid * 16 + t];
            int   kk = rki[tid * 16 + t];
            if (v < bv || (v == bv && kk < bi)) { bv = v; bi = kk; }
        }
        g_idx[n0 + tid] = bi;
    }
}

// ---------------- histogram of code usage ----------------
__global__ void k_counts() {
    int n = blockIdx.x * blockDim.x + threadIdx.x;
    if (n < NPTS) atomicAdd(&g_cnt[g_idx[n]], 1);
}

// ---------------- z_q_st + loss sum ----------------
__global__ void k_zq(const float* __restrict__ z, const float* __restrict__ cb,
                     float* __restrict__ out) {
    int i = blockIdx.x * blockDim.x + threadIdx.x;  // 16,777,216 elements
    int n = ((i >> 18) << 10) | (i & 1023);
    int c = (i >> 10) & 255;
    float ze = z[i];
    float zq = cb[(size_t)g_idx[n] * CDIM + c];
    float diff = __fsub_rn(zq, ze);
    out[i] = __fadd_rn(ze, diff);                    // z_e + (z_q - z_e)
    float sq = __fmul_rn(diff, diff);

    double v = (double)sq;
    #pragma unroll
    for (int off = 16; off; off >>= 1)
        v += __shfl_down_sync(0xffffffffu, v, off);
    __shared__ double ws[8];
    int lane = threadIdx.x & 31, w = threadIdx.x >> 5;
    if (lane == 0) ws[w] = v;
    __syncthreads();
    if (w == 0) {
        double t = (lane < 8) ? ws[lane] : 0.0;
        #pragma unroll
        for (int off = 4; off; off >>= 1)
            t += __shfl_down_sync(0xffffffffu, t, off);
        if (lane == 0) atomicAdd(&g_loss, t);
    }
}

// ---------------- one-hot encodings (float2; base offset is 8B-aligned) ----------------
__global__ void k_enc(float* __restrict__ out) {
    int gid = blockIdx.x * blockDim.x + threadIdx.x;  // 67,108,864 float2's
    int n  = gid >> 10;
    int k0 = (gid & 1023) << 1;
    int best = g_idx[n];
    float2 v;
    v.x = (k0     == best) ? 1.f : 0.f;
    v.y = (k0 + 1 == best) ? 1.f : 0.f;
    *(float2*)(out + OFF_ENC + (size_t)gid * 2) = v;
}

// ---------------- scalars: loss, perplexity ----------------
__global__ void k_scalars(float* __restrict__ out) {
    __shared__ double ssum[256];
    int t = threadIdx.x;
    double s = 0.0;
    for (int k = t; k < KCODES; k += 256) {
        float em = (float)g_cnt[k] * (1.0f / 65536.0f);   // exact (count * 2^-16)
        float lg = logf(__fadd_rn(em, 1e-10f));
        float term = __fmul_rn(em, lg);
        s += (double)term;
    }
    ssum[t] = s;
    __syncthreads();
    for (int off = 128; off; off >>= 1) {
        if (t < off) ssum[t] += ssum[t + off];
        __syncthreads();
    }
    if (t == 0) {
        float S = (float)ssum[0];
        out[OFF_PERP] = expf(-S);
        double m = g_loss / 16777216.0;
        float mf = (float)m;
        out[OFF_LOSS] = __fadd_rn(mf, __fmul_rn(0.25f, mf));  // (1 + 0.25) * mse
    }
}

extern "C" void kernel_launch(void* const* d_in, const int* in_sizes, int n_in,
                              void* d_out, int out_size) {
    (void)out_size;
    const float* z  = (const float*)d_in[0];
    const float* cb = (const float*)d_in[1];
    if (n_in >= 2 && in_sizes[0] == KCODES * CDIM) {  // defensive: swapped inputs
        const float* t = z; z = cb; cb = t;
    }
    float* out = (float*)d_out;

    const int dsmem = (256 * 128 + 64 * ESP + 64 + 128) * (int)sizeof(float); // 198,400 B
    cudaFuncSetAttribute(k_argmin, cudaFuncAttributeMaxDynamicSharedMemorySize, dsmem);

    k_prep   <<<(KCODES + 255) / 256, 256>>>(cb);
    k_argmin <<<NPTS / MT, TH, dsmem>>>(z, cb);
    k_counts <<<NPTS / 256, 256>>>();
    k_zq     <<<16777216 / 256, 256>>>(z, cb, out);
    k_enc    <<<67108864 / 256, 256>>>(out);
    k_scalars<<<1, 256>>>(out);
}

// round 3
// speedup vs baseline: 1.0004x; 1.0004x over previous
#include <cuda_runtime.h>
#include <math.h>

#define NPTS   65536
#define CDIM   256
#define KCODES 2048

#define MT 128      // points per block
#define KT 64       // codes per chunk
#define TH 512      // threads per block (main kernel)
#define ESP 260     // padded codebook smem row (floats)

// scratch (no allocations allowed)
__device__ int    g_idx[NPTS];
__device__ float  g_cbn[KCODES];
__device__ int    g_cnt[KCODES];
__device__ double g_loss;

// offsets in d_out (fp32): [z_q_st (16,777,216) | loss | perplexity | encodings (134,217,728)]
#define OFF_LOSS 16777216
#define OFF_PERP 16777217
#define OFF_ENC  16777218

// ---------------- codebook squared norms + zero counters ----------------
__global__ void k_prep(const float* __restrict__ cb) {
    int k = blockIdx.x * blockDim.x + threadIdx.x;
    if (k < KCODES) {
        const float* row = cb + (size_t)k * CDIM;
        float s = 0.f;
        #pragma unroll 8
        for (int c = 0; c < CDIM; ++c) {
            float t = row[c];
            s = __fadd_rn(s, __fmul_rn(t, t));
        }
        g_cbn[k] = s;
        g_cnt[k] = 0;
    }
    if (k == 0) g_loss = 0.0;
}

// ---------------- fused distance GEMM + argmin ----------------
// d[n,k] = fl( fl(A_n - 2*M[n,k]) + B_k ), argmin over k with first-index ties.
__global__ __launch_bounds__(TH, 1)
void k_argmin(const float* __restrict__ z, const float* __restrict__ cb) {
    extern __shared__ float sm[];
    float* zs = sm;                       // [256][128] : z tile, c-major
    float* es = zs + 256 * 128;           // [64][ESP]  : codebook chunk, padded
    float* bs = es + 64 * ESP;            // [64]       : ||e||^2 chunk
    float* as = bs + 64;                  // [128]      : A_n

    const int tid = threadIdx.x;
    const int tk  = tid & 15;             // 0..15  (code groups)
    const int tn  = tid >> 4;             // 0..31  (point groups, 4 each)

    const int blk = blockIdx.x;           // 0..511
    const int b   = blk >> 3;
    const int hw0 = (blk & 7) << 7;       // 128 contiguous hw
    const int n0  = blk * MT;

    const float* zb = z + ((size_t)b * CDIM) * 1024 + hw0;

    // ---- load z tile (coalesced float4), store as zs[c][j] ----
    for (int e = tid; e < 256 * 32; e += TH) {
        int c  = e >> 5;
        int j4 = (e & 31) << 2;
        float4 v = *(const float4*)(zb + (size_t)c * 1024 + j4);
        *(float4*)&zs[c * 128 + j4] = v;
    }
    __syncthreads();

    // ---- A_n = sum_c z^2, strided partials + butterfly tree ----
    if (tid < MT) {
        float p[32];
        #pragma unroll
        for (int l = 0; l < 32; ++l) p[l] = 0.f;
        #pragma unroll
        for (int i = 0; i < 8; ++i) {
            #pragma unroll
            for (int l = 0; l < 32; ++l) {
                float t = zs[(l + 32 * i) * 128 + tid];
                p[l] = __fadd_rn(p[l], __fmul_rn(t, t));
            }
        }
        #pragma unroll
        for (int off = 16; off >= 1; off >>= 1) {
            #pragma unroll
            for (int l = 0; l < 16; ++l) {
                if (l < off) p[l] = __fadd_rn(p[l], p[l + off]);
            }
        }
        as[tid] = p[0];
    }
    __syncthreads();

    float Ar[4];
    #pragma unroll
    for (int r = 0; r < 4; ++r) Ar[r] = as[tn * 4 + r];

    float mval[4];
    int   midx[4];
    #pragma unroll
    for (int r = 0; r < 4; ++r) { mval[r] = 3.4e38f; midx[r] = 0; }

    for (int kb = 0; kb < KCODES; kb += KT) {
        __syncthreads();  // previous chunk's readers done before overwrite
        // load 64 codebook rows (coalesced), padded rows kill bank conflicts
        for (int e = tid; e < 64 * 64; e += TH) {
            int j  = e >> 6;
            int c4 = (e & 63) << 2;
            float4 v = *(const float4*)(cb + (size_t)(kb + j) * CDIM + c4);
            *(float4*)&es[j * ESP + c4] = v;
        }
        if (tid < KT) bs[tid] = g_cbn[kb + tid];
        __syncthreads();

        float acc[4][4];
        #pragma unroll
        for (int r = 0; r < 4; ++r)
            #pragma unroll
            for (int q = 0; q < 4; ++q) acc[r][q] = 0.f;

        #pragma unroll 4
        for (int c0 = 0; c0 < 256; c0 += 4) {
            float4 zf[4], ef[4];
            #pragma unroll
            for (int i = 0; i < 4; ++i)
                zf[i] = *(float4*)&zs[(c0 + i) * 128 + tn * 4];
            #pragma unroll
            for (int q = 0; q < 4; ++q)
                ef[q] = *(float4*)&es[(tk + 16 * q) * ESP + c0];
            #pragma unroll
            for (int i = 0; i < 4; ++i) {
                float z0 = ((const float*)&zf[i])[0];
                float z1 = ((const float*)&zf[i])[1];
                float z2 = ((const float*)&zf[i])[2];
                float z3 = ((const float*)&zf[i])[3];
                #pragma unroll
                for (int q = 0; q < 4; ++q) {
                    float ev = ((const float*)&ef[q])[i];
                    acc[0][q] = fmaf(z0, ev, acc[0][q]);
                    acc[1][q] = fmaf(z1, ev, acc[1][q]);
                    acc[2][q] = fmaf(z2, ev, acc[2][q]);
                    acc[3][q] = fmaf(z3, ev, acc[3][q]);
                }
            }
        }

        // merge this chunk into running argmin (k ascending within thread)
        #pragma unroll
        for (int q = 0; q < 4; ++q) {
            int j = tk + 16 * q;
            int k = kb + j;
            float Bk = bs[j];
            #pragma unroll
            for (int r = 0; r < 4; ++r) {
                float d = __fadd_rn(__fadd_rn(Ar[r], -2.0f * acc[r][q]), Bk);
                if (d < mval[r]) { mval[r] = d; midx[r] = k; }
            }
        }
    }

    // ---- cross-thread (tk) reduction, tie -> smallest k ----
    __syncthreads();
    float* rv  = es;                    // reuse es: 128*16 floats
    int*   rki = (int*)(es + MT * 16);  // + 128*16 ints
    #pragma unroll
    for (int r = 0; r < 4; ++r) {
        int n = tn * 4 + r;
        rv [n * 16 + tk] = mval[r];
        rki[n * 16 + tk] = midx[r];
    }
    __syncthreads();
    if (tid < MT) {
        float bv = rv[tid * 16];
        int   bi = rki[tid * 16];
        #pragma unroll
        for (int t = 1; t < 16; ++t) {
            float v = rv[tid * 16 + t];
            int   kk = rki[tid * 16 + t];
            if (v < bv || (v == bv && kk < bi)) { bv = v; bi = kk; }
        }
        g_idx[n0 + tid] = bi;
    }
}

// ---------------- histogram of code usage ----------------
__global__ void k_counts() {
    int n = blockIdx.x * blockDim.x + threadIdx.x;
    if (n < NPTS) atomicAdd(&g_cnt[g_idx[n]], 1);
}

// ---------------- z_q_st + loss sum ----------------
__global__ void k_zq(const float* __restrict__ z, const float* __restrict__ cb,
                     float* __restrict__ out) {
    int i = blockIdx.x * blockDim.x + threadIdx.x;  // 16,777,216 elements
    int n = ((i >> 18) << 10) | (i & 1023);
    int c = (i >> 10) & 255;
    float ze = z[i];
    float zq = cb[(size_t)g_idx[n] * CDIM + c];
    float diff = __fsub_rn(zq, ze);
    out[i] = __fadd_rn(ze, diff);                    // z_e + (z_q - z_e)
    float sq = __fmul_rn(diff, diff);

    double v = (double)sq;
    #pragma unroll
    for (int off = 16; off; off >>= 1)
        v += __shfl_down_sync(0xffffffffu, v, off);
    __shared__ double ws[8];
    int lane = threadIdx.x & 31, w = threadIdx.x >> 5;
    if (lane == 0) ws[w] = v;
    __syncthreads();
    if (w == 0) {
        double t = (lane < 8) ? ws[lane] : 0.0;
        #pragma unroll
        for (int off = 4; off; off >>= 1)
            t += __shfl_down_sync(0xffffffffu, t, off);
        if (lane == 0) atomicAdd(&g_loss, t);
    }
}

// ---------------- one-hot encodings (float2; base offset is 8B-aligned) ----------------
__global__ void k_enc(float* __restrict__ out) {
    int gid = blockIdx.x * blockDim.x + threadIdx.x;  // 67,108,864 float2's
    int n  = gid >> 10;
    int k0 = (gid & 1023) << 1;
    int best = g_idx[n];
    float2 v;
    v.x = (k0     == best) ? 1.f : 0.f;
    v.y = (k0 + 1 == best) ? 1.f : 0.f;
    *(float2*)(out + OFF_ENC + (size_t)gid * 2) = v;
}

// ---------------- scalars: loss, perplexity ----------------
__global__ void k_scalars(float* __restrict__ out) {
    __shared__ double ssum[256];
    int t = threadIdx.x;
    double s = 0.0;
    for (int k = t; k < KCODES; k += 256) {
        float em = (float)g_cnt[k] * (1.0f / 65536.0f);   // exact (count * 2^-16)
        float lg = logf(__fadd_rn(em, 1e-10f));
        float term = __fmul_rn(em, lg);
        s += (double)term;
    }
    ssum[t] = s;
    __syncthreads();
    for (int off = 128; off; off >>= 1) {
        if (t < off) ssum[t] += ssum[t + off];
        __syncthreads();
    }
    if (t == 0) {
        float S = (float)ssum[0];
        out[OFF_PERP] = expf(-S);
        double m = g_loss / 16777216.0;
        float mf = (float)m;
        out[OFF_LOSS] = __fadd_rn(mf, __fmul_rn(0.25f, mf));  // (1 + 0.25) * mse
    }
}

extern "C" void kernel_launch(void* const* d_in, const int* in_sizes, int n_in,
                              void* d_out, int out_size) {
    (void)out_size;
    const float* z  = (const float*)d_in[0];
    const float* cb = (const float*)d_in[1];
    if (n_in >= 2 && in_sizes[0] == KCODES * CDIM) {  // defensive: swapped inputs
        const float* t = z; z = cb; cb = t;
    }
    float* out = (float*)d_out;

    const int dsmem = (256 * 128 + 64 * ESP + 64 + 128) * (int)sizeof(float); // 198,400 B
    cudaFuncSetAttribute(k_argmin, cudaFuncAttributeMaxDynamicSharedMemorySize, dsmem);

    k_prep   <<<(KCODES + 255) / 256, 256>>>(cb);
    k_argmin <<<NPTS / MT, TH, dsmem>>>(z, cb);
    k_counts <<<NPTS / 256, 256>>>();
    k_zq     <<<16777216 / 256, 256>>>(z, cb, out);
    k_enc    <<<67108864 / 256, 256>>>(out);
    k_scalars<<<1, 256>>>(out);
}